// round 9
// baseline (speedup 1.0000x reference)
#include <cuda_runtime.h>
#include <cstdint>
#include <cfloat>

#define NB 256
#define NQ 1000
#define NC 80
#define TOPK 300
#define NPAD 1024
#define T 512
#define TILE_ROWS 128
#define TILES (NB * NQ / TILE_ROWS)   // 2000
#define GRID 592                      // 4 CTAs/SM x 148 SMs: all resident

typedef unsigned long long ull;

// packed keys: [ordered score 32b | (1023-q) 10b | label 10b]
__device__ ull g_keys[NB * NQ];
__device__ int g_cnt[NB];             // zero-init; each launch restores zeros

__device__ __forceinline__ unsigned f2ord(float f) {
    unsigned u = __float_as_uint(f);
    return (u & 0x80000000u) ? ~u : (u | 0x80000000u);
}
__device__ __forceinline__ float ord2f(unsigned u) {
    return (u & 0x80000000u) ? __uint_as_float(u & 0x7FFFFFFFu)
                             : __uint_as_float(~u);
}
__device__ __forceinline__ void cswap(ull& a, ull& c, bool desc) {
    if (desc ? (a < c) : (a > c)) { ull t = a; a = c; c = t; }
}
__device__ __forceinline__ ull kmax(ull a, ull b) { return a > b ? a : b; }
__device__ __forceinline__ ull kmin(ull a, ull b) { return a < b ? a : b; }

// ---------------------------------------------------------------------------
// In-CTA sort+emit for one batch: 512 threads x 2 keys register bitonic.
//   j=1       : in-thread swap
//   j=2..32   : shfl_xor (m <= 16)
//   j=64..512 : smem exchange
// Keys unique => exact stable jax.lax.top_k order.
// ---------------------------------------------------------------------------
__device__ void sort_emit(int b, ull* sh,
                          const float* __restrict__ pboxes,
                          const float* __restrict__ tsizes,
                          float* __restrict__ out)
{
    const int tid  = threadIdx.x;
    const int lane = tid & 31;

    ull v0 = 0, v1 = 0;
    if (tid < NQ / 2) {   // 500; 16B-aligned (b*8000 bytes)
        ulonglong2 x = __ldcg((const ulonglong2*)(g_keys + (size_t)b * NQ) + tid);
        v0 = x.x; v1 = x.y;
    }

    cswap(v0, v1, (tid & 1) == 0);    // k = 2

    for (int k = 4; k <= NPAD; k <<= 1) {
        const bool up = (((tid << 1) & k) == 0);

        for (int j = k >> 1; j >= 64; j >>= 1) {     // smem steps
            int m = j >> 1;
            sh[tid] = v0; sh[T + tid] = v1;
            __syncthreads();
            bool km = up != ((tid & m) != 0);
            int  p  = tid ^ m;
            ull p0 = sh[p], p1 = sh[T + p];
            v0 = km ? kmax(v0, p0) : kmin(v0, p0);
            v1 = km ? kmax(v1, p1) : kmin(v1, p1);
            __syncthreads();
        }

        int js = (k >> 1) < 32 ? (k >> 1) : 32;      // shfl steps
        for (int j = js; j >= 2; j >>= 1) {
            int m = j >> 1;
            bool km = up != ((lane & m) != 0);
            ull p0 = __shfl_xor_sync(0xffffffffu, v0, m);
            ull p1 = __shfl_xor_sync(0xffffffffu, v1, m);
            v0 = km ? kmax(v0, p0) : kmin(v0, p0);
            v1 = km ? kmax(v1, p1) : kmin(v1, p1);
        }

        cswap(v0, v1, up);                           // j = 1
    }

    if (tid < (TOPK + 1) / 2) { sh[2 * tid] = v0; sh[2 * tid + 1] = v1; }
    __syncthreads();

    if (tid < TOPK) {
        const float img_h = tsizes[b * 2 + 0];
        const float img_w = tsizes[b * 2 + 1];
        ull key     = sh[tid];
        float s     = ord2f((unsigned)(key >> 32));
        int   q     = 1023 - (int)((key >> 10) & 0x3FFu);
        int   label = (int)(key & 0x3FFu);
        bool  valid = s > 0.05f;

        int o = b * TOPK + tid;
        out[o]             = valid ? s : 0.0f;
        out[NB * TOPK + o] = valid ? (float)label : -1.0f;

        float4 rr = make_float4(0.f, 0.f, 0.f, 0.f);
        if (valid) {
            float4 pb = *(const float4*)(pboxes + ((size_t)b * NQ + q) * 4);
            rr.x = (pb.x - 0.5f * pb.z) * img_w;
            rr.y = (pb.y - 0.5f * pb.w) * img_h;
            rr.z = (pb.x + 0.5f * pb.z) * img_w;
            rr.w = (pb.y + 0.5f * pb.w) * img_h;
        }
        *(float4*)(out + 2 * NB * TOPK + (size_t)o * 4) = rr;
    }
    __syncthreads();   // close sh before reuse
}

// ---------------------------------------------------------------------------
// Persistent fused kernel: 592 resident CTAs grid-stride over 2000 tiles.
// Last CTA to complete a batch sorts+emits it inline; no wave gating.
// ---------------------------------------------------------------------------
__global__ __launch_bounds__(T)
void fused_kernel(const float* __restrict__ logits,
                  const float* __restrict__ pboxes,
                  const float* __restrict__ tsizes,
                  float* __restrict__ out)
{
    __shared__ __align__(16) float smf[TILE_ROWS * 81];
    __shared__ int s_sort[2];
    ull* sh = (ull*)smf;

    const int tid = threadIdx.x;

    for (int t = blockIdx.x; t < TILES; t += GRID) {
        // ---- score phase: tile-streaming max/argmax ----
        {
            const size_t f4base = (size_t)t * (TILE_ROWS * NC / 4);
            const float4* src = (const float4*)logits + f4base;

            float4 v[5];
            #pragma unroll
            for (int i = 0; i < 5; i++) v[i] = __ldcs(src + tid + T * i);

            #pragma unroll
            for (int i = 0; i < 5; i++) {
                int fl = (tid + T * i) * 4;
                int r  = fl / NC;
                int c  = fl - r * NC;
                float* d = &smf[r * 81 + c];
                d[0] = v[i].x; d[1] = v[i].y; d[2] = v[i].z; d[3] = v[i].w;
            }
            __syncthreads();

            const int r  = tid >> 2;
            const int qt = tid & 3;
            const float* row = &smf[r * 81 + qt * 20];
            float best = row[0]; int bi = 0;
            #pragma unroll
            for (int i = 1; i < 20; i++) {
                float x = row[i];
                if (x > best) { best = x; bi = i; }
            }
            bi += qt * 20;
            #pragma unroll
            for (int off = 2; off; off >>= 1) {
                float ov = __shfl_down_sync(0xffffffffu, best, off);
                int   oi = __shfl_down_sync(0xffffffffu, bi,  off);
                if (ov > best) { best = ov; bi = oi; }
            }

            if (qt == 0) {
                int g  = t * TILE_ROWS + r;
                int b  = g / NQ;
                int qq = g - b * NQ;
                float s  = 1.0f / (1.0f + expf(-best));
                float ms = (s > 0.05f) ? s : -1.0f;
                g_keys[g] = ((ull)f2ord(ms) << 32) | ((ull)(1023 - qq) << 10) | (unsigned)bi;
            }
        }
        __syncthreads();     // tile keys stored; smf reads done

        // ---- completion accounting (last-arriver sorts) ----
        if (tid == 0) {
            __threadfence();                       // release: publish keys
            int lo = t * TILE_ROWS;
            int hi = lo + TILE_ROWS;
            int b0 = lo / NQ;
            int b1 = (hi - 1) / NQ;
            s_sort[0] = -1; s_sort[1] = -1;

            int c0 = min(hi, (b0 + 1) * NQ) - lo;
            if (atomicAdd(&g_cnt[b0], c0) + c0 == NQ) s_sort[0] = b0;
            if (b1 != b0) {
                int c1 = hi - b1 * NQ;
                if (atomicAdd(&g_cnt[b1], c1) + c1 == NQ) s_sort[1] = b1;
            }
            if (s_sort[0] >= 0 || s_sort[1] >= 0) __threadfence();  // acquire
        }
        __syncthreads();

        // ---- sort any batch this CTA completed ----
        #pragma unroll
        for (int s = 0; s < 2; s++) {
            int b = s_sort[s];
            if (b >= 0) {
                sort_emit(b, sh, pboxes, tsizes, out);
                if (tid == 0) g_cnt[b] = 0;        // restore for next launch
            }
        }
        __syncthreads();     // s_sort / sh settled before next tile
    }
}

extern "C" void kernel_launch(void* const* d_in, const int* in_sizes, int n_in,
                              void* d_out, int out_size) {
    const float* logits = (const float*)d_in[0];  // (256,1000,80)
    const float* boxes  = (const float*)d_in[1];  // (256,1000,4)
    const float* tsz    = (const float*)d_in[2];  // (256,2)
    float* out = (float*)d_out;

    fused_kernel<<<GRID, T>>>(logits, boxes, tsz, out);   // 592 persistent CTAs
}

// round 10
// speedup vs baseline: 2.3071x; 2.3071x over previous
#include <cuda_runtime.h>
#include <cstdint>

#define NB 256
#define NQ 1000
#define NC 80
#define TOPK 300
#define NPAD 1024
#define T 1024
#define TROWS 125                      // rows per tile; 8 * 125 = 1000 exactly
#define NTILES 8
#define F4T (TROWS * NC / 4)           // 2500 float4 per tile

typedef unsigned long long ull;

__device__ __forceinline__ unsigned f2ord(float f) {
    unsigned u = __float_as_uint(f);
    return (u & 0x80000000u) ? ~u : (u | 0x80000000u);
}
__device__ __forceinline__ float ord2f(unsigned u) {
    return (u & 0x80000000u) ? __uint_as_float(u & 0x7FFFFFFFu)
                             : __uint_as_float(~u);
}
__device__ __forceinline__ ull kmax(ull a, ull b) { return a > b ? a : b; }
__device__ __forceinline__ ull kmin(ull a, ull b) { return a < b ? a : b; }

// ---------------------------------------------------------------------------
// One CTA = one batch. Stream 8 tiles of 125 rows through smem (de-swizzle +
// 4-threads/row reduce), keys accumulate in smem, then in-CTA bitonic sort of
// 1024 keys (1/thread) and emit. No global scratch, no fences, no atomics.
// ---------------------------------------------------------------------------
__global__ __launch_bounds__(T, 2)
void fused_kernel(const float* __restrict__ logits,
                  const float* __restrict__ pboxes,
                  const float* __restrict__ tsizes,
                  float* __restrict__ out)
{
    __shared__ __align__(16) float smf[TROWS * 81];   // 40500 B tile buffer
    __shared__ ull skeys[NPAD];                       // 8192 B keys
    ull* sh = (ull*)smf;                              // sort exchange reuses tile buf

    const int b    = blockIdx.x;
    const int tid  = threadIdx.x;
    const int lane = tid & 31;

    if (tid < NPAD - NQ) skeys[NQ + tid] = 0ULL;      // padding = minimal key

    const float4* src = (const float4*)logits + (size_t)b * (NQ * NC / 4);

    // ================= streaming phase: 8 tiles ==================
    for (int t = 0; t < NTILES; t++) {
        const float4* tsrc = src + t * F4T;

        float4 v[3];
        bool   ok[3];
        #pragma unroll
        for (int i = 0; i < 3; i++) {                 // all loads issued first
            int idx4 = tid + T * i;
            ok[i] = idx4 < F4T;
            if (ok[i]) v[i] = __ldcs(tsrc + idx4);
        }
        #pragma unroll
        for (int i = 0; i < 3; i++) {                 // de-swizzle, stride-81
            if (ok[i]) {
                int fl = (tid + T * i) * 4;
                int r  = fl / NC;
                int c  = fl - r * NC;
                float* d = &smf[r * 81 + c];
                d[0] = v[i].x; d[1] = v[i].y; d[2] = v[i].z; d[3] = v[i].w;
            }
        }
        __syncthreads();

        // 4 threads per row, 20 cols each; threads with r>=TROWS compute junk
        // on a clamped address (kept convergent for the shfls) and discard.
        const int r  = tid >> 2;
        const int qt = tid & 3;
        const int rr = r < TROWS ? r : TROWS - 1;
        const float* row = &smf[rr * 81 + qt * 20];
        float best = row[0]; int bi = 0;
        #pragma unroll
        for (int i = 1; i < 20; i++) {
            float x = row[i];
            if (x > best) { best = x; bi = i; }       // strict > : lowest index
        }
        bi += qt * 20;
        #pragma unroll
        for (int off = 2; off; off >>= 1) {
            float ov = __shfl_down_sync(0xffffffffu, best, off);
            int   oi = __shfl_down_sync(0xffffffffu, bi,  off);
            if (ov > best) { best = ov; bi = oi; }
        }

        if (qt == 0 && r < TROWS) {
            int qq = t * TROWS + r;
            float s  = 1.0f / (1.0f + expf(-best));   // sigmoid monotone
            float ms = (s > 0.05f) ? s : -1.0f;
            skeys[qq] = ((ull)f2ord(ms) << 32) | ((ull)(1023 - qq) << 10) | (unsigned)bi;
        }
        __syncthreads();                              // smf free for next tile
    }

    // ================= sort phase: bitonic 1024, 1 key/thread ==========
    // keepmax = up != side with up = ((tid&k)==0) gives DESCENDING order.
    ull v = skeys[tid];
    for (int k = 2; k <= NPAD; k <<= 1) {
        const bool up = (tid & k) == 0;

        for (int j = k >> 1; j >= 32; j >>= 1) {      // cross-warp via smem
            sh[tid] = v;
            __syncthreads();
            bool km = up != ((tid & j) != 0);
            ull  p  = sh[tid ^ j];
            v = km ? kmax(v, p) : kmin(v, p);
            __syncthreads();
        }
        int js = (k >> 1) < 16 ? (k >> 1) : 16;       // intra-warp via shfl
        for (int j = js; j >= 1; j >>= 1) {
            bool km = up != ((tid & j) != 0);
            ull  p  = __shfl_xor_sync(0xffffffffu, v, j);
            v = km ? kmax(v, p) : kmin(v, p);
        }
    }
    sh[tid] = v;
    __syncthreads();

    // ================= emit top-300 ==================
    if (tid < TOPK) {
        const float img_h = tsizes[b * 2 + 0];
        const float img_w = tsizes[b * 2 + 1];
        ull key     = sh[tid];
        float s     = ord2f((unsigned)(key >> 32));
        int   q     = 1023 - (int)((key >> 10) & 0x3FFu);
        int   label = (int)(key & 0x3FFu);
        bool  valid = s > 0.05f;

        int o = b * TOPK + tid;
        out[o]             = valid ? s : 0.0f;
        out[NB * TOPK + o] = valid ? (float)label : -1.0f;

        float4 rr = make_float4(0.f, 0.f, 0.f, 0.f);
        if (valid) {
            float4 pb = *(const float4*)(pboxes + ((size_t)b * NQ + q) * 4);
            rr.x = (pb.x - 0.5f * pb.z) * img_w;
            rr.y = (pb.y - 0.5f * pb.w) * img_h;
            rr.z = (pb.x + 0.5f * pb.z) * img_w;
            rr.w = (pb.y + 0.5f * pb.w) * img_h;
        }
        *(float4*)(out + 2 * NB * TOPK + (size_t)o * 4) = rr;
    }
}

extern "C" void kernel_launch(void* const* d_in, const int* in_sizes, int n_in,
                              void* d_out, int out_size) {
    const float* logits = (const float*)d_in[0];  // (256,1000,80)
    const float* boxes  = (const float*)d_in[1];  // (256,1000,4)
    const float* tsz    = (const float*)d_in[2];  // (256,2)
    float* out = (float*)d_out;

    fused_kernel<<<NB, T>>>(logits, boxes, tsz, out);   // 1 CTA per batch
}